// round 9
// baseline (speedup 1.0000x reference)
#include <cuda_runtime.h>
#include <cuda_bf16.h>
#include <math.h>
#include <stdint.h>

// ---------------------------------------------------------------------------
// PairContrastiveLoss via mma.sync (HMMA bf16), fused softmax/lse epilogue.
//   emb = im2col(x|y) @ W^T + b   (bf16 inputs, fp32 accum, fused im2col)
//   CE[i,j] = (L[i] - S[i,j]) / 196,  S = Xp_raw @ q^T, L[i] = sum_p lse
//   out = (trace/B) / ((sum-trace)/(B^2-B))
// ---------------------------------------------------------------------------

#define BSZ   64
#define NP    196
#define HID   384
#define KDIM  768
#define MROWS 12544
#define KTOT  75264
#define SK    128          // k-chunk for S gemm
#define NKB   588          // KTOT / SK

__device__ __nv_bfloat16 g_Wt[KDIM * HID];                  // [k][n] bf16
__device__ __nv_bfloat16 g_Xb[(size_t)MROWS * HID];         // raw x logits bf16
__device__ __nv_bfloat16 g_Qb[(size_t)MROWS * HID];         // q = softmax(y) bf16
__device__ float g_lse[MROWS];
__device__ float g_L[BSZ];
__device__ float g_Spart[NKB * 4096];
__device__ float g_S[4096];

// ------------------------------------------------------------- PTX helpers
__device__ __forceinline__ uint32_t smem_u32(const void* p) {
    uint32_t a;
    asm("{ .reg .u64 t; cvta.to.shared.u64 t, %1; cvt.u32.u64 %0, t; }"
        : "=r"(a) : "l"(p));
    return a;
}
__device__ __forceinline__ void cp_async16(uint32_t dst, const void* src) {
    asm volatile("cp.async.cg.shared.global [%0], [%1], 16;" :: "r"(dst), "l"(src));
}
#define CP_COMMIT() asm volatile("cp.async.commit_group;" ::: "memory")
#define CP_WAIT(n)  asm volatile("cp.async.wait_group %0;" :: "n"(n) : "memory")

__device__ __forceinline__ void ldm_x4(uint32_t* r, uint32_t addr) {
    asm volatile("ldmatrix.sync.aligned.m8n8.x4.shared.b16 {%0,%1,%2,%3}, [%4];"
        : "=r"(r[0]), "=r"(r[1]), "=r"(r[2]), "=r"(r[3]) : "r"(addr));
}
__device__ __forceinline__ void ldm_x4t(uint32_t* r, uint32_t addr) {
    asm volatile("ldmatrix.sync.aligned.m8n8.x4.trans.shared.b16 {%0,%1,%2,%3}, [%4];"
        : "=r"(r[0]), "=r"(r[1]), "=r"(r[2]), "=r"(r[3]) : "r"(addr));
}
__device__ __forceinline__ void mma16816(float* d, const uint32_t* a,
                                         uint32_t b0, uint32_t b1) {
    asm volatile(
        "mma.sync.aligned.m16n8k16.row.col.f32.bf16.bf16.f32 "
        "{%0,%1,%2,%3}, {%4,%5,%6,%7}, {%8,%9}, {%0,%1,%2,%3};"
        : "+f"(d[0]), "+f"(d[1]), "+f"(d[2]), "+f"(d[3])
        : "r"(a[0]), "r"(a[1]), "r"(a[2]), "r"(a[3]), "r"(b0), "r"(b1));
}

// ------------------------------------------------------------------ prep W
__global__ void k_prep_w(const float* __restrict__ Wc) {
    int idx = blockIdx.x * 256 + threadIdx.x;
    if (idx < KDIM * HID) {
        int k = idx / HID, n = idx - k * HID;
        g_Wt[idx] = __float2bfloat16_rn(Wc[n * KDIM + k]);
    }
}

// ------------------------------------------------ HMMA patch-embed GEMM
// CTA: BM=128 x BN=384 (full N), BK=32, 24 k-iters, 512 threads (4m x 4n warps).
// Epilogue: bias + full-row softmax(y)->q bf16 / raw bf16 + lse (x).
#define APAD   40
#define BPAD   392
#define A_ST   (128 * APAD * 2)         // 10240 B
#define B_ST   (32 * BPAD * 2)          // 25088 B
#define SM_A0  0
#define SM_A1  A_ST
#define SM_B0  (2 * A_ST)
#define SM_B1  (2 * A_ST + B_ST)
#define SM_GEMM (2 * A_ST + 2 * B_ST)   // 70656 B

__global__ void __launch_bounds__(512, 1) k_gemm(
        const float* __restrict__ x, const float* __restrict__ y,
        const float* __restrict__ bias) {
    extern __shared__ char smem[];
    const uint32_t sb = smem_u32(smem);
    const int tid = threadIdx.x;
    const int lane = tid & 31;
    const int wid = tid >> 5;
    const int wm = wid >> 2;            // 0..3
    const int wn = wid & 3;             // 0..3
    const int m0 = blockIdx.x * 128;
    const int img = blockIdx.y;
    const float* im = img ? y : x;

    // A-load geometry: row r_a (0..127), seg pair s_a / s_a+4 (same col4)
    const int r_a = tid >> 2;
    const int s_a = tid & 3;
    const int col4 = s_a * 4;
    int base_a;
    {
        int m = m0 + r_a;
        int b = m / NP, p = m - b * NP;
        int ph = p / 14, pw = p - ph * 14;
        base_a = (b * 3 * 224 + ph * 16) * 224 + pw * 16 + col4;
    }
    const uint32_t a_dst_e = r_a * APAD + s_a * 4;   // srr=0; srr=1 adds +16

    const uint32_t Aoff[2] = {SM_A0, SM_A1};
    const uint32_t Boff[2] = {SM_B0, SM_B1};

    float acc[2][12][4] = {};

    auto issueB = [&](int j, int buf) {
        #pragma unroll
        for (int it = 0; it < 3; ++it) {
            int idx = tid + it * 512;
            int row = idx / 48, seg = idx - row * 48;
            cp_async16(sb + Boff[buf] + row * (BPAD * 2) + seg * 16,
                       g_Wt + (size_t)(j * 32 + row) * HID + seg * 8);
        }
        CP_COMMIT();
    };
    auto ldgA = [&](int j, float4* av) {
        const int c = j >> 3, r0 = (j & 7) * 2;
        const int off = base_a + c * 50176 + r0 * 224;
        av[0] = *(const float4*)(im + off);
        av[1] = *(const float4*)(im + off + 224);
    };
    auto stsA = [&](int buf, const float4* av) {
        #pragma unroll
        for (int h = 0; h < 2; ++h) {
            __nv_bfloat162 p0 = __floats2bfloat162_rn(av[h].x, av[h].y);
            __nv_bfloat162 p1 = __floats2bfloat162_rn(av[h].z, av[h].w);
            char* d = smem + Aoff[buf] + (a_dst_e + h * 16) * 2;
            *(uint32_t*)d       = *(uint32_t*)&p0;
            *(uint32_t*)(d + 4) = *(uint32_t*)&p1;
        }
    };

    {
        float4 av[2];
        ldgA(0, av);
        stsA(0, av);
        issueB(0, 0);
    }

    float4 nxt[2];
    for (int j = 0; j < 24; ++j) {
        const int buf = j & 1;
        if (j < 23) {
            ldgA(j + 1, nxt);
            issueB(j + 1, buf ^ 1);
            CP_WAIT(1);
        } else {
            CP_WAIT(0);
        }
        __syncthreads();

        const uint32_t aBase = sb + Aoff[buf];
        const uint32_t bBase = sb + Boff[buf];
        #pragma unroll
        for (int kf2 = 0; kf2 < 2; ++kf2) {
            const int kf = kf2 * 16;
            uint32_t a[2][4];
            #pragma unroll
            for (int mf = 0; mf < 2; ++mf) {
                uint32_t ad = aBase +
                    ((wm * 32 + mf * 16 + (lane & 15)) * APAD + kf + ((lane >> 4) << 3)) * 2;
                ldm_x4(a[mf], ad);
            }
            #pragma unroll
            for (int nf2 = 0; nf2 < 6; ++nf2) {
                uint32_t bb[4];
                uint32_t bd = bBase +
                    ((kf + (lane & 15)) * BPAD + wn * 96 + nf2 * 16 + ((lane >> 4) << 3)) * 2;
                ldm_x4t(bb, bd);
                mma16816(acc[0][nf2 * 2 + 0], a[0], bb[0], bb[1]);
                mma16816(acc[0][nf2 * 2 + 1], a[0], bb[2], bb[3]);
                mma16816(acc[1][nf2 * 2 + 0], a[1], bb[0], bb[1]);
                mma16816(acc[1][nf2 * 2 + 1], a[1], bb[2], bb[3]);
            }
        }

        if (j < 23) stsA(buf ^ 1, nxt);
        __syncthreads();
    }

    // ================= fused epilogue: bias + softmax/lse =================
    const int qid = lane >> 2, tc = lane & 3;

    #pragma unroll
    for (int nf = 0; nf < 12; ++nf) {
        float2 bv = *(const float2*)(bias + wn * 96 + nf * 8 + tc * 2);
        #pragma unroll
        for (int mf = 0; mf < 2; ++mf) {
            acc[mf][nf][0] += bv.x; acc[mf][nf][1] += bv.y;
            acc[mf][nf][2] += bv.x; acc[mf][nf][3] += bv.y;
        }
    }

    float* sMax = (float*)smem;              // [128][4]
    float* sSum = (float*)(smem + 2048);     // [128][4]

    float mx[2][2];
    #pragma unroll
    for (int mf = 0; mf < 2; ++mf)
        #pragma unroll
        for (int h = 0; h < 2; ++h) {
            float m = -1e30f;
            #pragma unroll
            for (int nf = 0; nf < 12; ++nf)
                m = fmaxf(m, fmaxf(acc[mf][nf][h * 2], acc[mf][nf][h * 2 + 1]));
            m = fmaxf(m, __shfl_xor_sync(0xffffffffu, m, 1));
            m = fmaxf(m, __shfl_xor_sync(0xffffffffu, m, 2));
            mx[mf][h] = m;
        }
    if (tc == 0) {
        #pragma unroll
        for (int mf = 0; mf < 2; ++mf)
            #pragma unroll
            for (int h = 0; h < 2; ++h)
                sMax[(wm * 32 + mf * 16 + h * 8 + qid) * 4 + wn] = mx[mf][h];
    }
    __syncthreads();
    float gmx[2][2];
    #pragma unroll
    for (int mf = 0; mf < 2; ++mf)
        #pragma unroll
        for (int h = 0; h < 2; ++h) {
            const float* r = &sMax[(wm * 32 + mf * 16 + h * 8 + qid) * 4];
            gmx[mf][h] = fmaxf(fmaxf(r[0], r[1]), fmaxf(r[2], r[3]));
        }
    float sm[2][2];
    #pragma unroll
    for (int mf = 0; mf < 2; ++mf)
        #pragma unroll
        for (int h = 0; h < 2; ++h) {
            float s = 0.0f;
            #pragma unroll
            for (int nf = 0; nf < 12; ++nf)
                s += __expf(acc[mf][nf][h * 2] - gmx[mf][h])
                   + __expf(acc[mf][nf][h * 2 + 1] - gmx[mf][h]);
            s += __shfl_xor_sync(0xffffffffu, s, 1);
            s += __shfl_xor_sync(0xffffffffu, s, 2);
            sm[mf][h] = s;
        }
    __syncthreads();
    if (tc == 0) {
        #pragma unroll
        for (int mf = 0; mf < 2; ++mf)
            #pragma unroll
            for (int h = 0; h < 2; ++h)
                sSum[(wm * 32 + mf * 16 + h * 8 + qid) * 4 + wn] = sm[mf][h];
    }
    __syncthreads();

    __nv_bfloat16* dst = img ? g_Qb : g_Xb;
    #pragma unroll
    for (int mf = 0; mf < 2; ++mf) {
        #pragma unroll
        for (int h = 0; h < 2; ++h) {
            const int mloc = wm * 32 + mf * 16 + h * 8 + qid;
            const int row = m0 + mloc;
            const float* r = &sSum[mloc * 4];
            const float den = r[0] + r[1] + r[2] + r[3];
            if (img == 0) {
                if (wn == 0 && tc == 0) g_lse[row] = gmx[mf][h] + __logf(den);
                #pragma unroll
                for (int nf = 0; nf < 12; ++nf) {
                    __nv_bfloat162 p = __floats2bfloat162_rn(
                        acc[mf][nf][h * 2], acc[mf][nf][h * 2 + 1]);
                    *(uint32_t*)(dst + (size_t)row * HID + wn * 96 + nf * 8 + tc * 2)
                        = *(uint32_t*)&p;
                }
            } else {
                const float inv = 1.0f / den;
                const float g = gmx[mf][h];
                #pragma unroll
                for (int nf = 0; nf < 12; ++nf) {
                    __nv_bfloat162 p = __floats2bfloat162_rn(
                        __expf(acc[mf][nf][h * 2] - g) * inv,
                        __expf(acc[mf][nf][h * 2 + 1] - g) * inv);
                    *(uint32_t*)(dst + (size_t)row * HID + wn * 96 + nf * 8 + tc * 2)
                        = *(uint32_t*)&p;
                }
            }
        }
    }
}

// ----------------------------------------------------- L[b] = sum_p lse[b,p]
__global__ void k_reduceL() {
    const int b = blockIdx.x;
    const int tid = threadIdx.x;
    float v = (tid < NP) ? g_lse[b * NP + tid] : 0.0f;
    #pragma unroll
    for (int o = 16; o; o >>= 1) v += __shfl_xor_sync(0xffffffffu, v, o);
    __shared__ float red[8];
    if ((tid & 31) == 0) red[tid >> 5] = v;
    __syncthreads();
    if (tid == 0) {
        float s = 0.0f;
        #pragma unroll
        for (int w = 0; w < 8; ++w) s += red[w];
        g_L[b] = s;
    }
}

// ---------------- S partials via HMMA: block = one 128-wide k slice
#define SPAD 136                        // SK + 8 elems
__global__ void __launch_bounds__(256) k_sgemm() {
    extern __shared__ char sh[];
    __nv_bfloat16* Xs = (__nv_bfloat16*)sh;
    __nv_bfloat16* Qs = (__nv_bfloat16*)(sh + 64 * SPAD * 2);
    const uint32_t xb = smem_u32(Xs), qb = smem_u32(Qs);
    const int tid = threadIdx.x;
    const int lane = tid & 31;
    const int wid = tid >> 5;
    const int wm2 = wid >> 1;           // 0..3
    const int wn2 = wid & 1;            // 0..1

    const uint4* Xu = (const uint4*)g_Xb;
    const uint4* Qu = (const uint4*)g_Qb;
    const int kb16 = blockIdx.x * 16;   // uint4 offset in row (128 elems)
    #pragma unroll
    for (int it = 0; it < 4; ++it) {
        int u = tid + it * 256;
        int row = u >> 4, un = u & 15;
        *(uint4*)(Xs + row * SPAD + un * 8) = Xu[(size_t)row * 9408 + kb16 + un];
        *(uint4*)(Qs + row * SPAD + un * 8) = Qu[(size_t)row * 9408 + kb16 + un];
    }
    __syncthreads();

    float acc[4][4] = {};
    #pragma unroll 4
    for (int ks = 0; ks < 8; ++ks) {
        const uint32_t koff = (ks * 16 + ((lane >> 4) << 3)) * 2;
        uint32_t a[4], b0[4], b1[4];
        ldm_x4(a,  xb + (wm2 * 16 + (lane & 15)) * (SPAD * 2) + koff);
        ldm_x4(b0, qb + (wn2 * 32 + (lane & 15)) * (SPAD * 2) + koff);
        ldm_x4(b1, qb + (wn2 * 32 + 16 + (lane & 15)) * (SPAD * 2) + koff);
        mma16816(acc[0], a, b0[0], b0[1]);
        mma16816(acc[1], a, b0[2], b0[3]);
        mma16816(acc[2], a, b1[0], b1[1]);
        mma16816(acc[3], a, b1[2], b1[3]);
    }

    float* dst = g_Spart + (size_t)blockIdx.x * 4096;
    const int qid = lane >> 2, tc = lane & 3;
    #pragma unroll
    for (int t = 0; t < 4; ++t) {
        int i0 = wm2 * 16 + qid;
        int j  = wn2 * 32 + t * 8 + tc * 2;
        *(float2*)(dst + i0 * 64 + j)       = make_float2(acc[t][0], acc[t][1]);
        *(float2*)(dst + (i0 + 8) * 64 + j) = make_float2(acc[t][2], acc[t][3]);
    }
}

__global__ void k_sreduce() {
    int idx = blockIdx.x * 256 + threadIdx.x;   // 4096
    float s = 0.0f;
    #pragma unroll 2
    for (int b = 0; b < NKB; ++b) s += g_Spart[(size_t)b * 4096 + idx];
    g_S[idx] = s;
}

// ------------------------------------------------------------- final scalar
__global__ void k_final(float* __restrict__ out) {
    const int tid = threadIdx.x;
    float tot = 0.0f, diag = 0.0f;
    for (int idx = tid; idx < 4096; idx += 256) {
        int i = idx >> 6, j = idx & 63;
        float ce = (g_L[i] - g_S[idx]) * (1.0f / 196.0f);
        tot += ce;
        if (i == j) diag += ce;
    }
    #pragma unroll
    for (int o = 16; o; o >>= 1) {
        tot  += __shfl_xor_sync(0xffffffffu, tot,  o);
        diag += __shfl_xor_sync(0xffffffffu, diag, o);
    }
    __shared__ float rt[8], rd[8];
    if ((tid & 31) == 0) { rt[tid >> 5] = tot; rd[tid >> 5] = diag; }
    __syncthreads();
    if (tid == 0) {
        float T = 0.0f, D = 0.0f;
        #pragma unroll
        for (int w = 0; w < 8; ++w) { T += rt[w]; D += rd[w]; }
        out[0] = (D / 64.0f) / ((T - D) / 4032.0f);
    }
}

// ---------------------------------------------------------------------------
extern "C" void kernel_launch(void* const* d_in, const int* in_sizes, int n_in,
                              void* d_out, int out_size) {
    const float* x  = (const float*)d_in[0];
    const float* y  = (const float*)d_in[1];
    const float* Wc = (const float*)d_in[2];
    const float* b  = (const float*)d_in[3];
    float* out = (float*)d_out;

    const int SM_S = 2 * 64 * SPAD * 2;   // 34816 B

    cudaFuncSetAttribute(k_gemm, cudaFuncAttributeMaxDynamicSharedMemorySize, SM_GEMM);
    cudaFuncSetAttribute(k_sgemm, cudaFuncAttributeMaxDynamicSharedMemorySize, SM_S);

    k_prep_w<<<(KDIM * HID + 255) / 256, 256>>>(Wc);
    k_gemm<<<dim3(98, 2), 512, SM_GEMM>>>(x, y, b);
    k_reduceL<<<BSZ, 256>>>();
    k_sgemm<<<NKB, 256, SM_S>>>();
    k_sreduce<<<16, 256>>>();
    k_final<<<1, 256>>>(out);
}

// round 10
// speedup vs baseline: 1.3281x; 1.3281x over previous
#include <cuda_runtime.h>
#include <cuda_bf16.h>
#include <math.h>
#include <stdint.h>

// ---------------------------------------------------------------------------
// PairContrastiveLoss via mma.sync (HMMA bf16), fused softmax/lse epilogue.
//   emb = im2col(x|y) @ W^T + b   (bf16 inputs, fp32 accum, fused im2col)
//   CE[i,j] = (L[i] - S[i,j]) / 196,  S = Xp_raw @ q^T, L[i] = sum_p lse
//   out = (trace/B) / ((sum-trace)/(B^2-B))
// R10: R7 config (BM=64, 256 thr, SK=256) + 2 CTAs/SM on k_gemm.
// ---------------------------------------------------------------------------

#define BSZ   64
#define NP    196
#define HID   384
#define KDIM  768
#define MROWS 12544
#define KTOT  75264
#define SK    256          // k-chunk for S gemm
#define NKB   294          // KTOT / SK

__device__ __nv_bfloat16 g_Wt[KDIM * HID];                  // [k][n] bf16
__device__ __nv_bfloat16 g_Xb[(size_t)MROWS * HID];         // raw x logits bf16
__device__ __nv_bfloat16 g_Qb[(size_t)MROWS * HID];         // q = softmax(y) bf16
__device__ float g_lse[MROWS];
__device__ float g_L[BSZ];
__device__ float g_Spart[NKB * 4096];
__device__ float g_S[4096];

// ------------------------------------------------------------- PTX helpers
__device__ __forceinline__ uint32_t smem_u32(const void* p) {
    uint32_t a;
    asm("{ .reg .u64 t; cvta.to.shared.u64 t, %1; cvt.u32.u64 %0, t; }"
        : "=r"(a) : "l"(p));
    return a;
}
__device__ __forceinline__ void cp_async16(uint32_t dst, const void* src) {
    asm volatile("cp.async.cg.shared.global [%0], [%1], 16;" :: "r"(dst), "l"(src));
}
#define CP_COMMIT() asm volatile("cp.async.commit_group;" ::: "memory")
#define CP_WAIT(n)  asm volatile("cp.async.wait_group %0;" :: "n"(n) : "memory")

__device__ __forceinline__ void ldm_x4(uint32_t* r, uint32_t addr) {
    asm volatile("ldmatrix.sync.aligned.m8n8.x4.shared.b16 {%0,%1,%2,%3}, [%4];"
        : "=r"(r[0]), "=r"(r[1]), "=r"(r[2]), "=r"(r[3]) : "r"(addr));
}
__device__ __forceinline__ void ldm_x4t(uint32_t* r, uint32_t addr) {
    asm volatile("ldmatrix.sync.aligned.m8n8.x4.trans.shared.b16 {%0,%1,%2,%3}, [%4];"
        : "=r"(r[0]), "=r"(r[1]), "=r"(r[2]), "=r"(r[3]) : "r"(addr));
}
__device__ __forceinline__ void mma16816(float* d, const uint32_t* a,
                                         uint32_t b0, uint32_t b1) {
    asm volatile(
        "mma.sync.aligned.m16n8k16.row.col.f32.bf16.bf16.f32 "
        "{%0,%1,%2,%3}, {%4,%5,%6,%7}, {%8,%9}, {%0,%1,%2,%3};"
        : "+f"(d[0]), "+f"(d[1]), "+f"(d[2]), "+f"(d[3])
        : "r"(a[0]), "r"(a[1]), "r"(a[2]), "r"(a[3]), "r"(b0), "r"(b1));
}

// ------------------------------------------------------------------ prep W
__global__ void k_prep_w(const float* __restrict__ Wc) {
    int idx = blockIdx.x * 256 + threadIdx.x;
    if (idx < KDIM * HID) {
        int k = idx / HID, n = idx - k * HID;
        g_Wt[idx] = __float2bfloat16_rn(Wc[n * KDIM + k]);
    }
}

// ------------------------------------------------ HMMA patch-embed GEMM
// CTA: BM=64 x BN=384 (full N), BK=32, 24 k-iters, 8 warps (2m x 4n).
// 2 CTAs/SM for latency hiding. Epilogue: bias + softmax(y)/lse(x), bf16 out.
#define APAD   40
#define BPAD   392
#define A_ST   (64 * APAD * 2)
#define B_ST   (32 * BPAD * 2)
#define SM_A0  0
#define SM_A1  A_ST
#define SM_B0  (2 * A_ST)
#define SM_B1  (2 * A_ST + B_ST)
#define SM_GEMM (2 * A_ST + 2 * B_ST)   // 60416 B

__global__ void __launch_bounds__(256, 2) k_gemm(
        const float* __restrict__ x, const float* __restrict__ y,
        const float* __restrict__ bias) {
    extern __shared__ char smem[];
    const uint32_t sb = smem_u32(smem);
    const int tid = threadIdx.x;
    const int lane = tid & 31;
    const int wid = tid >> 5;
    const int wm = wid >> 2;            // 0..1
    const int wn = wid & 3;             // 0..3
    const int m0 = blockIdx.x * 64;
    const int img = blockIdx.y;
    const float* im = img ? y : x;

    const int r_a = tid >> 3;
    const int s_a = tid & 7;
    const int srr  = s_a >> 2;
    const int col4 = (s_a & 3) * 4;
    int base_r[2];
    #pragma unroll
    for (int h = 0; h < 2; ++h) {
        int m = m0 + r_a + h * 32;
        int b = m / NP, p = m - b * NP;
        int ph = p / 14, pw = p - ph * 14;
        base_r[h] = (b * 3 * 224 + ph * 16) * 224 + pw * 16 + col4;
    }
    const uint32_t a_dst_e = r_a * APAD + srr * 16 + (s_a & 3) * 4;

    const uint32_t Aoff[2] = {SM_A0, SM_A1};
    const uint32_t Boff[2] = {SM_B0, SM_B1};

    float acc[2][12][4] = {};

    auto issueB = [&](int j, int buf) {
        #pragma unroll
        for (int it = 0; it < 6; ++it) {
            int idx = tid + it * 256;
            int row = idx / 48, seg = idx - row * 48;
            cp_async16(sb + Boff[buf] + row * (BPAD * 2) + seg * 16,
                       g_Wt + (size_t)(j * 32 + row) * HID + seg * 8);
        }
        CP_COMMIT();
    };
    auto ldgA = [&](int j, float4* av) {
        const int c = j >> 3, r0 = (j & 7) * 2;
        const int off = c * 50176 + (r0 + srr) * 224;
        av[0] = *(const float4*)(im + base_r[0] + off);
        av[1] = *(const float4*)(im + base_r[1] + off);
    };
    auto stsA = [&](int buf, const float4* av) {
        #pragma unroll
        for (int h = 0; h < 2; ++h) {
            __nv_bfloat162 p0 = __floats2bfloat162_rn(av[h].x, av[h].y);
            __nv_bfloat162 p1 = __floats2bfloat162_rn(av[h].z, av[h].w);
            char* d = smem + Aoff[buf] + (a_dst_e + h * 32 * APAD) * 2;
            *(uint32_t*)d       = *(uint32_t*)&p0;
            *(uint32_t*)(d + 4) = *(uint32_t*)&p1;
        }
    };

    {
        float4 av[2];
        ldgA(0, av);
        stsA(0, av);
        issueB(0, 0);
    }

    float4 nxt[2];
    for (int j = 0; j < 24; ++j) {
        const int buf = j & 1;
        if (j < 23) {
            ldgA(j + 1, nxt);
            issueB(j + 1, buf ^ 1);
            CP_WAIT(1);
        } else {
            CP_WAIT(0);
        }
        __syncthreads();

        const uint32_t aBase = sb + Aoff[buf];
        const uint32_t bBase = sb + Boff[buf];
        #pragma unroll
        for (int kf2 = 0; kf2 < 2; ++kf2) {
            const int kf = kf2 * 16;
            uint32_t a[2][4];
            #pragma unroll
            for (int mf = 0; mf < 2; ++mf) {
                uint32_t ad = aBase +
                    ((wm * 32 + mf * 16 + (lane & 15)) * APAD + kf + ((lane >> 4) << 3)) * 2;
                ldm_x4(a[mf], ad);
            }
            #pragma unroll
            for (int nf2 = 0; nf2 < 6; ++nf2) {
                uint32_t bb[4];
                uint32_t bd = bBase +
                    ((kf + (lane & 15)) * BPAD + wn * 96 + nf2 * 16 + ((lane >> 4) << 3)) * 2;
                ldm_x4t(bb, bd);
                mma16816(acc[0][nf2 * 2 + 0], a[0], bb[0], bb[1]);
                mma16816(acc[0][nf2 * 2 + 1], a[0], bb[2], bb[3]);
                mma16816(acc[1][nf2 * 2 + 0], a[1], bb[0], bb[1]);
                mma16816(acc[1][nf2 * 2 + 1], a[1], bb[2], bb[3]);
            }
        }

        if (j < 23) stsA(buf ^ 1, nxt);
        __syncthreads();
    }

    // ================= fused epilogue: bias + softmax/lse =================
    const int qid = lane >> 2, tc = lane & 3;

    #pragma unroll
    for (int nf = 0; nf < 12; ++nf) {
        float2 bv = *(const float2*)(bias + wn * 96 + nf * 8 + tc * 2);
        #pragma unroll
        for (int mf = 0; mf < 2; ++mf) {
            acc[mf][nf][0] += bv.x; acc[mf][nf][1] += bv.y;
            acc[mf][nf][2] += bv.x; acc[mf][nf][3] += bv.y;
        }
    }

    float* sMax = (float*)smem;              // [64][4]
    float* sSum = (float*)(smem + 1024);     // [64][4]

    float mx[2][2];
    #pragma unroll
    for (int mf = 0; mf < 2; ++mf)
        #pragma unroll
        for (int h = 0; h < 2; ++h) {
            float m = -1e30f;
            #pragma unroll
            for (int nf = 0; nf < 12; ++nf)
                m = fmaxf(m, fmaxf(acc[mf][nf][h * 2], acc[mf][nf][h * 2 + 1]));
            m = fmaxf(m, __shfl_xor_sync(0xffffffffu, m, 1));
            m = fmaxf(m, __shfl_xor_sync(0xffffffffu, m, 2));
            mx[mf][h] = m;
        }
    if (tc == 0) {
        #pragma unroll
        for (int mf = 0; mf < 2; ++mf)
            #pragma unroll
            for (int h = 0; h < 2; ++h)
                sMax[(wm * 32 + mf * 16 + h * 8 + qid) * 4 + wn] = mx[mf][h];
    }
    __syncthreads();
    float gmx[2][2];
    #pragma unroll
    for (int mf = 0; mf < 2; ++mf)
        #pragma unroll
        for (int h = 0; h < 2; ++h) {
            const float* r = &sMax[(wm * 32 + mf * 16 + h * 8 + qid) * 4];
            gmx[mf][h] = fmaxf(fmaxf(r[0], r[1]), fmaxf(r[2], r[3]));
        }
    float sm[2][2];
    #pragma unroll
    for (int mf = 0; mf < 2; ++mf)
        #pragma unroll
        for (int h = 0; h < 2; ++h) {
            float s = 0.0f;
            #pragma unroll
            for (int nf = 0; nf < 12; ++nf)
                s += __expf(acc[mf][nf][h * 2] - gmx[mf][h])
                   + __expf(acc[mf][nf][h * 2 + 1] - gmx[mf][h]);
            s += __shfl_xor_sync(0xffffffffu, s, 1);
            s += __shfl_xor_sync(0xffffffffu, s, 2);
            sm[mf][h] = s;
        }
    __syncthreads();
    if (tc == 0) {
        #pragma unroll
        for (int mf = 0; mf < 2; ++mf)
            #pragma unroll
            for (int h = 0; h < 2; ++h)
                sSum[(wm * 32 + mf * 16 + h * 8 + qid) * 4 + wn] = sm[mf][h];
    }
    __syncthreads();

    __nv_bfloat16* dst = img ? g_Qb : g_Xb;
    #pragma unroll
    for (int mf = 0; mf < 2; ++mf) {
        #pragma unroll
        for (int h = 0; h < 2; ++h) {
            const int mloc = wm * 32 + mf * 16 + h * 8 + qid;
            const int row = m0 + mloc;
            const float* r = &sSum[mloc * 4];
            const float den = r[0] + r[1] + r[2] + r[3];
            if (img == 0) {
                if (wn == 0 && tc == 0) g_lse[row] = gmx[mf][h] + __logf(den);
                #pragma unroll
                for (int nf = 0; nf < 12; ++nf) {
                    __nv_bfloat162 p = __floats2bfloat162_rn(
                        acc[mf][nf][h * 2], acc[mf][nf][h * 2 + 1]);
                    *(uint32_t*)(dst + (size_t)row * HID + wn * 96 + nf * 8 + tc * 2)
                        = *(uint32_t*)&p;
                }
            } else {
                const float inv = 1.0f / den;
                const float g = gmx[mf][h];
                #pragma unroll
                for (int nf = 0; nf < 12; ++nf) {
                    __nv_bfloat162 p = __floats2bfloat162_rn(
                        __expf(acc[mf][nf][h * 2] - g) * inv,
                        __expf(acc[mf][nf][h * 2 + 1] - g) * inv);
                    *(uint32_t*)(dst + (size_t)row * HID + wn * 96 + nf * 8 + tc * 2)
                        = *(uint32_t*)&p;
                }
            }
        }
    }
}

// ----------------------------------------------------- L[b] = sum_p lse[b,p]
__global__ void k_reduceL() {
    const int b = blockIdx.x;
    const int tid = threadIdx.x;
    float v = (tid < NP) ? g_lse[b * NP + tid] : 0.0f;
    #pragma unroll
    for (int o = 16; o; o >>= 1) v += __shfl_xor_sync(0xffffffffu, v, o);
    __shared__ float red[8];
    if ((tid & 31) == 0) red[tid >> 5] = v;
    __syncthreads();
    if (tid == 0) {
        float s = 0.0f;
        #pragma unroll
        for (int w = 0; w < 8; ++w) s += red[w];
        g_L[b] = s;
    }
}

// ---------------- S partials via HMMA: block = one 256-wide k slice
#define SPAD 264                        // SK + 8 elems
__global__ void __launch_bounds__(256) k_sgemm() {
    extern __shared__ char sh[];
    __nv_bfloat16* Xs = (__nv_bfloat16*)sh;
    __nv_bfloat16* Qs = (__nv_bfloat16*)(sh + 64 * SPAD * 2);
    const uint32_t xb = smem_u32(Xs), qb = smem_u32(Qs);
    const int tid = threadIdx.x;
    const int lane = tid & 31;
    const int wid = tid >> 5;
    const int wm2 = wid >> 1;           // 0..3
    const int wn2 = wid & 1;            // 0..1

    const uint4* Xu = (const uint4*)g_Xb;
    const uint4* Qu = (const uint4*)g_Qb;
    const int kb32 = blockIdx.x * 32;
    #pragma unroll
    for (int it = 0; it < 8; ++it) {
        int u = tid + it * 256;
        int row = u >> 5, un = u & 31;
        *(uint4*)(Xs + row * SPAD + un * 8) = Xu[(size_t)row * 9408 + kb32 + un];
        *(uint4*)(Qs + row * SPAD + un * 8) = Qu[(size_t)row * 9408 + kb32 + un];
    }
    __syncthreads();

    float acc[4][4] = {};
    #pragma unroll 4
    for (int ks = 0; ks < 16; ++ks) {
        const uint32_t koff = (ks * 16 + ((lane >> 4) << 3)) * 2;
        uint32_t a[4], b0[4], b1[4];
        ldm_x4(a,  xb + (wm2 * 16 + (lane & 15)) * (SPAD * 2) + koff);
        ldm_x4(b0, qb + (wn2 * 32 + (lane & 15)) * (SPAD * 2) + koff);
        ldm_x4(b1, qb + (wn2 * 32 + 16 + (lane & 15)) * (SPAD * 2) + koff);
        mma16816(acc[0], a, b0[0], b0[1]);
        mma16816(acc[1], a, b0[2], b0[3]);
        mma16816(acc[2], a, b1[0], b1[1]);
        mma16816(acc[3], a, b1[2], b1[3]);
    }

    float* dst = g_Spart + (size_t)blockIdx.x * 4096;
    const int qid = lane >> 2, tc = lane & 3;
    #pragma unroll
    for (int t = 0; t < 4; ++t) {
        int i0 = wm2 * 16 + qid;
        int j  = wn2 * 32 + t * 8 + tc * 2;
        *(float2*)(dst + i0 * 64 + j)       = make_float2(acc[t][0], acc[t][1]);
        *(float2*)(dst + (i0 + 8) * 64 + j) = make_float2(acc[t][2], acc[t][3]);
    }
}

__global__ void k_sreduce() {
    int idx = blockIdx.x * 256 + threadIdx.x;   // 4096
    float s = 0.0f;
    #pragma unroll 2
    for (int b = 0; b < NKB; ++b) s += g_Spart[(size_t)b * 4096 + idx];
    g_S[idx] = s;
}

// ------------------------------------------------------------- final scalar
__global__ void k_final(float* __restrict__ out) {
    const int tid = threadIdx.x;
    float tot = 0.0f, diag = 0.0f;
    for (int idx = tid; idx < 4096; idx += 256) {
        int i = idx >> 6, j = idx & 63;
        float ce = (g_L[i] - g_S[idx]) * (1.0f / 196.0f);
        tot += ce;
        if (i == j) diag += ce;
    }
    #pragma unroll
    for (int o = 16; o; o >>= 1) {
        tot  += __shfl_xor_sync(0xffffffffu, tot,  o);
        diag += __shfl_xor_sync(0xffffffffu, diag, o);
    }
    __shared__ float rt[8], rd[8];
    if ((tid & 31) == 0) { rt[tid >> 5] = tot; rd[tid >> 5] = diag; }
    __syncthreads();
    if (tid == 0) {
        float T = 0.0f, D = 0.0f;
        #pragma unroll
        for (int w = 0; w < 8; ++w) { T += rt[w]; D += rd[w]; }
        out[0] = (D / 64.0f) / ((T - D) / 4032.0f);
    }
}

// ---------------------------------------------------------------------------
extern "C" void kernel_launch(void* const* d_in, const int* in_sizes, int n_in,
                              void* d_out, int out_size) {
    const float* x  = (const float*)d_in[0];
    const float* y  = (const float*)d_in[1];
    const float* Wc = (const float*)d_in[2];
    const float* b  = (const float*)d_in[3];
    float* out = (float*)d_out;

    const int SM_S = 2 * 64 * SPAD * 2;   // 67584 B

    cudaFuncSetAttribute(k_gemm, cudaFuncAttributeMaxDynamicSharedMemorySize, SM_GEMM);
    cudaFuncSetAttribute(k_sgemm, cudaFuncAttributeMaxDynamicSharedMemorySize, SM_S);

    k_prep_w<<<(KDIM * HID + 255) / 256, 256>>>(Wc);
    k_gemm<<<dim3(196, 2), 256, SM_GEMM>>>(x, y, b);
    k_reduceL<<<BSZ, 256>>>();
    k_sgemm<<<NKB, 256, SM_S>>>();
    k_sreduce<<<16, 256>>>();
    k_final<<<1, 256>>>(out);
}

// round 11
// speedup vs baseline: 1.4064x; 1.0589x over previous
#include <cuda_runtime.h>
#include <cuda_bf16.h>
#include <math.h>
#include <stdint.h>

// ---------------------------------------------------------------------------
// PairContrastiveLoss via mma.sync (HMMA bf16), fused softmax/lse epilogue.
//   emb = im2col(x|y) @ W^T + b   (A: fp32 cp.async + in-reg bf16 cvt)
//   CE[i,j] = (L[i] - S[i,j]) / 196,  S = Xp_raw @ q^T, L[i] = sum_p lse
//   out = (trace/B) / ((sum-trace)/(B^2-B))
// R11: 3-stage cp.async pipeline, 1 barrier/iter, A fp32 in smem.
// ---------------------------------------------------------------------------

#define BSZ   64
#define NP    196
#define HID   384
#define KDIM  768
#define MROWS 12544
#define KTOT  75264
#define SK    256          // k-chunk for S gemm
#define NKB   294          // KTOT / SK

__device__ __nv_bfloat16 g_Wt[KDIM * HID];                  // [k][n] bf16
__device__ __nv_bfloat16 g_Xb[(size_t)MROWS * HID];         // raw x logits bf16
__device__ __nv_bfloat16 g_Qb[(size_t)MROWS * HID];         // q = softmax(y) bf16
__device__ float g_lse[MROWS];
__device__ float g_L[BSZ];
__device__ float g_Spart[NKB * 4096];
__device__ float g_S[4096];

// ------------------------------------------------------------- PTX helpers
__device__ __forceinline__ uint32_t smem_u32(const void* p) {
    uint32_t a;
    asm("{ .reg .u64 t; cvta.to.shared.u64 t, %1; cvt.u32.u64 %0, t; }"
        : "=r"(a) : "l"(p));
    return a;
}
__device__ __forceinline__ void cp_async16(uint32_t dst, const void* src) {
    asm volatile("cp.async.cg.shared.global [%0], [%1], 16;" :: "r"(dst), "l"(src));
}
#define CP_COMMIT() asm volatile("cp.async.commit_group;" ::: "memory")
#define CP_WAIT(n)  asm volatile("cp.async.wait_group %0;" :: "n"(n) : "memory")

__device__ __forceinline__ void ldm_x4t(uint32_t* r, uint32_t addr) {
    asm volatile("ldmatrix.sync.aligned.m8n8.x4.trans.shared.b16 {%0,%1,%2,%3}, [%4];"
        : "=r"(r[0]), "=r"(r[1]), "=r"(r[2]), "=r"(r[3]) : "r"(addr));
}
__device__ __forceinline__ void mma16816(float* d, const uint32_t* a,
                                         uint32_t b0, uint32_t b1) {
    asm volatile(
        "mma.sync.aligned.m16n8k16.row.col.f32.bf16.bf16.f32 "
        "{%0,%1,%2,%3}, {%4,%5,%6,%7}, {%8,%9}, {%0,%1,%2,%3};"
        : "+f"(d[0]), "+f"(d[1]), "+f"(d[2]), "+f"(d[3])
        : "r"(a[0]), "r"(a[1]), "r"(a[2]), "r"(a[3]), "r"(b0), "r"(b1));
}
__device__ __forceinline__ uint32_t packbf(float2 v) {
    __nv_bfloat162 p = __floats2bfloat162_rn(v.x, v.y);
    return *(uint32_t*)&p;
}

// ------------------------------------------------------------------ prep W
__global__ void k_prep_w(const float* __restrict__ Wc) {
    int idx = blockIdx.x * 256 + threadIdx.x;
    if (idx < KDIM * HID) {
        int k = idx / HID, n = idx - k * HID;
        g_Wt[idx] = __float2bfloat16_rn(Wc[n * KDIM + k]);
    }
}

// ------------------------------------------------ HMMA patch-embed GEMM
// CTA: BM=64 x BN=384 (full N), BK=32, 24 k-iters, 8 warps (2m x 4n).
// 3-stage cp.async (A fp32 + B bf16), single barrier per iter, 2 CTAs/SM.
#define APITCH 40                        // fp32 pitch: 8-bank row offset
#define BPAD   392
#define A_ST   (64 * APITCH * 4)         // 10240 B per stage (fp32)
#define B_ST   (32 * BPAD * 2)           // 25088 B per stage
#define NSTG   3
#define SM_B0  (NSTG * A_ST)             // 30720
#define SM_GEMM (NSTG * (A_ST + B_ST))   // 105984 B

__global__ void __launch_bounds__(256, 2) k_gemm(
        const float* __restrict__ x, const float* __restrict__ y,
        const float* __restrict__ bias) {
    extern __shared__ char smem[];
    const uint32_t sb = smem_u32(smem);
    const int tid = threadIdx.x;
    const int lane = tid & 31;
    const int wid = tid >> 5;
    const int wm = wid >> 2;            // 0..1
    const int wn = wid & 3;             // 0..3
    const int m0 = blockIdx.x * 64;
    const int img = blockIdx.y;
    const float* im = img ? y : x;

    // ---- A cp.async geometry: u = tid + it*256 -> row=u>>3, rr=(u>>2)&1, seg=u&3
    const int r_a = tid >> 3;           // 0..31 (it adds +32)
    const int rr  = (tid >> 2) & 1;
    const int seg = tid & 3;
    int baseA[2];
    uint32_t dstA[2];
    #pragma unroll
    for (int it = 0; it < 2; ++it) {
        int row = r_a + it * 32;
        int m = m0 + row;
        int b = m / NP, p = m - b * NP;
        int ph = p / 14, pw = p - ph * 14;
        baseA[it] = (b * 3 * 224 + ph * 16) * 224 + pw * 16 + rr * 224 + seg * 4;
        dstA[it]  = (row * APITCH + rr * 16 + seg * 4) * 4;
    }

    float acc[2][12][4] = {};

    auto issueStage = [&](int j, int buf) {
        const uint32_t aB = sb + buf * A_ST;
        const uint32_t bB = sb + SM_B0 + buf * B_ST;
        const int c = j >> 3, r2 = (j & 7) * 2;
        const int srcOff = c * 50176 + r2 * 224;
        #pragma unroll
        for (int it = 0; it < 2; ++it)
            cp_async16(aB + dstA[it], im + baseA[it] + srcOff);
        #pragma unroll
        for (int it = 0; it < 6; ++it) {
            int idx = tid + it * 256;
            int row = idx / 48, sg = idx - row * 48;
            cp_async16(bB + row * (BPAD * 2) + sg * 16,
                       g_Wt + (size_t)(j * 32 + row) * HID + sg * 8);
        }
        CP_COMMIT();
    };

    issueStage(0, 0);
    issueStage(1, 1);

    const int gr = lane >> 2;           // A frag row-in-8
    const int tg = (lane & 3) * 2;      // A frag col pair

    for (int j = 0; j < 24; ++j) {
        const int buf = j % NSTG;
        if (j < 23) { CP_WAIT(1); } else { CP_WAIT(0); }
        __syncthreads();
        if (j < 22) issueStage(j + 2, (j + 2) % NSTG);

        const float* Af = (const float*)(smem + buf * A_ST);
        const uint32_t bBase = sb + SM_B0 + buf * B_ST;
        #pragma unroll
        for (int kf2 = 0; kf2 < 2; ++kf2) {
            const int kf = kf2 * 16;
            uint32_t a[2][4];
            #pragma unroll
            for (int mf = 0; mf < 2; ++mf) {
                const float* base = Af + (wm * 32 + mf * 16) * APITCH + kf + tg;
                a[mf][0] = packbf(*(const float2*)(base + gr * APITCH));
                a[mf][1] = packbf(*(const float2*)(base + (gr + 8) * APITCH));
                a[mf][2] = packbf(*(const float2*)(base + gr * APITCH + 8));
                a[mf][3] = packbf(*(const float2*)(base + (gr + 8) * APITCH + 8));
            }
            #pragma unroll
            for (int nf2 = 0; nf2 < 6; ++nf2) {
                uint32_t bb[4];
                uint32_t bd = bBase +
                    ((kf + (lane & 15)) * BPAD + wn * 96 + nf2 * 16 + ((lane >> 4) << 3)) * 2;
                ldm_x4t(bb, bd);
                mma16816(acc[0][nf2 * 2 + 0], a[0], bb[0], bb[1]);
                mma16816(acc[0][nf2 * 2 + 1], a[0], bb[2], bb[3]);
                mma16816(acc[1][nf2 * 2 + 0], a[1], bb[0], bb[1]);
                mma16816(acc[1][nf2 * 2 + 1], a[1], bb[2], bb[3]);
            }
        }
    }
    __syncthreads();

    // ================= fused epilogue: bias + softmax/lse =================
    const int qid = lane >> 2, tc = lane & 3;

    #pragma unroll
    for (int nf = 0; nf < 12; ++nf) {
        float2 bv = *(const float2*)(bias + wn * 96 + nf * 8 + tc * 2);
        #pragma unroll
        for (int mf = 0; mf < 2; ++mf) {
            acc[mf][nf][0] += bv.x; acc[mf][nf][1] += bv.y;
            acc[mf][nf][2] += bv.x; acc[mf][nf][3] += bv.y;
        }
    }

    float* sMax = (float*)smem;              // [64][4]
    float* sSum = (float*)(smem + 1024);     // [64][4]

    float mx[2][2];
    #pragma unroll
    for (int mf = 0; mf < 2; ++mf)
        #pragma unroll
        for (int h = 0; h < 2; ++h) {
            float m = -1e30f;
            #pragma unroll
            for (int nf = 0; nf < 12; ++nf)
                m = fmaxf(m, fmaxf(acc[mf][nf][h * 2], acc[mf][nf][h * 2 + 1]));
            m = fmaxf(m, __shfl_xor_sync(0xffffffffu, m, 1));
            m = fmaxf(m, __shfl_xor_sync(0xffffffffu, m, 2));
            mx[mf][h] = m;
        }
    if (tc == 0) {
        #pragma unroll
        for (int mf = 0; mf < 2; ++mf)
            #pragma unroll
            for (int h = 0; h < 2; ++h)
                sMax[(wm * 32 + mf * 16 + h * 8 + qid) * 4 + wn] = mx[mf][h];
    }
    __syncthreads();
    float gmx[2][2];
    #pragma unroll
    for (int mf = 0; mf < 2; ++mf)
        #pragma unroll
        for (int h = 0; h < 2; ++h) {
            const float* r = &sMax[(wm * 32 + mf * 16 + h * 8 + qid) * 4];
            gmx[mf][h] = fmaxf(fmaxf(r[0], r[1]), fmaxf(r[2], r[3]));
        }
    float sm[2][2];
    #pragma unroll
    for (int mf = 0; mf < 2; ++mf)
        #pragma unroll
        for (int h = 0; h < 2; ++h) {
            float s = 0.0f;
            #pragma unroll
            for (int nf = 0; nf < 12; ++nf)
                s += __expf(acc[mf][nf][h * 2] - gmx[mf][h])
                   + __expf(acc[mf][nf][h * 2 + 1] - gmx[mf][h]);
            s += __shfl_xor_sync(0xffffffffu, s, 1);
            s += __shfl_xor_sync(0xffffffffu, s, 2);
            sm[mf][h] = s;
        }
    __syncthreads();
    if (tc == 0) {
        #pragma unroll
        for (int mf = 0; mf < 2; ++mf)
            #pragma unroll
            for (int h = 0; h < 2; ++h)
                sSum[(wm * 32 + mf * 16 + h * 8 + qid) * 4 + wn] = sm[mf][h];
    }
    __syncthreads();

    __nv_bfloat16* dst = img ? g_Qb : g_Xb;
    #pragma unroll
    for (int mf = 0; mf < 2; ++mf) {
        #pragma unroll
        for (int h = 0; h < 2; ++h) {
            const int mloc = wm * 32 + mf * 16 + h * 8 + qid;
            const int row = m0 + mloc;
            const float* r = &sSum[mloc * 4];
            const float den = r[0] + r[1] + r[2] + r[3];
            if (img == 0) {
                if (wn == 0 && tc == 0) g_lse[row] = gmx[mf][h] + __logf(den);
                #pragma unroll
                for (int nf = 0; nf < 12; ++nf) {
                    __nv_bfloat162 p = __floats2bfloat162_rn(
                        acc[mf][nf][h * 2], acc[mf][nf][h * 2 + 1]);
                    *(uint32_t*)(dst + (size_t)row * HID + wn * 96 + nf * 8 + tc * 2)
                        = *(uint32_t*)&p;
                }
            } else {
                const float inv = 1.0f / den;
                const float g = gmx[mf][h];
                #pragma unroll
                for (int nf = 0; nf < 12; ++nf) {
                    __nv_bfloat162 p = __floats2bfloat162_rn(
                        __expf(acc[mf][nf][h * 2] - g) * inv,
                        __expf(acc[mf][nf][h * 2 + 1] - g) * inv);
                    *(uint32_t*)(dst + (size_t)row * HID + wn * 96 + nf * 8 + tc * 2)
                        = *(uint32_t*)&p;
                }
            }
        }
    }
}

// ----------------------------------------------------- L[b] = sum_p lse[b,p]
__global__ void k_reduceL() {
    const int b = blockIdx.x;
    const int tid = threadIdx.x;
    float v = (tid < NP) ? g_lse[b * NP + tid] : 0.0f;
    #pragma unroll
    for (int o = 16; o; o >>= 1) v += __shfl_xor_sync(0xffffffffu, v, o);
    __shared__ float red[8];
    if ((tid & 31) == 0) red[tid >> 5] = v;
    __syncthreads();
    if (tid == 0) {
        float s = 0.0f;
        #pragma unroll
        for (int w = 0; w < 8; ++w) s += red[w];
        g_L[b] = s;
    }
}

// ---------------- S partials via HMMA: block = one 256-wide k slice
#define SPAD 264                        // SK + 8 elems
__device__ __forceinline__ void ldm_x4(uint32_t* r, uint32_t addr) {
    asm volatile("ldmatrix.sync.aligned.m8n8.x4.shared.b16 {%0,%1,%2,%3}, [%4];"
        : "=r"(r[0]), "=r"(r[1]), "=r"(r[2]), "=r"(r[3]) : "r"(addr));
}
__global__ void __launch_bounds__(256) k_sgemm() {
    extern __shared__ char sh[];
    __nv_bfloat16* Xs = (__nv_bfloat16*)sh;
    __nv_bfloat16* Qs = (__nv_bfloat16*)(sh + 64 * SPAD * 2);
    const uint32_t xb = smem_u32(Xs), qb = smem_u32(Qs);
    const int tid = threadIdx.x;
    const int lane = tid & 31;
    const int wid = tid >> 5;
    const int wm2 = wid >> 1;           // 0..3
    const int wn2 = wid & 1;            // 0..1

    const uint4* Xu = (const uint4*)g_Xb;
    const uint4* Qu = (const uint4*)g_Qb;
    const int kb32 = blockIdx.x * 32;
    #pragma unroll
    for (int it = 0; it < 8; ++it) {
        int u = tid + it * 256;
        int row = u >> 5, un = u & 31;
        *(uint4*)(Xs + row * SPAD + un * 8) = Xu[(size_t)row * 9408 + kb32 + un];
        *(uint4*)(Qs + row * SPAD + un * 8) = Qu[(size_t)row * 9408 + kb32 + un];
    }
    __syncthreads();

    float acc[4][4] = {};
    #pragma unroll 4
    for (int ks = 0; ks < 16; ++ks) {
        const uint32_t koff = (ks * 16 + ((lane >> 4) << 3)) * 2;
        uint32_t a[4], b0[4], b1[4];
        ldm_x4(a,  xb + (wm2 * 16 + (lane & 15)) * (SPAD * 2) + koff);
        ldm_x4(b0, qb + (wn2 * 32 + (lane & 15)) * (SPAD * 2) + koff);
        ldm_x4(b1, qb + (wn2 * 32 + 16 + (lane & 15)) * (SPAD * 2) + koff);
        mma16816(acc[0], a, b0[0], b0[1]);
        mma16816(acc[1], a, b0[2], b0[3]);
        mma16816(acc[2], a, b1[0], b1[1]);
        mma16816(acc[3], a, b1[2], b1[3]);
    }

    float* dst = g_Spart + (size_t)blockIdx.x * 4096;
    const int qid = lane >> 2, tc = lane & 3;
    #pragma unroll
    for (int t = 0; t < 4; ++t) {
        int i0 = wm2 * 16 + qid;
        int j  = wn2 * 32 + t * 8 + tc * 2;
        *(float2*)(dst + i0 * 64 + j)       = make_float2(acc[t][0], acc[t][1]);
        *(float2*)(dst + (i0 + 8) * 64 + j) = make_float2(acc[t][2], acc[t][3]);
    }
}

__global__ void k_sreduce() {
    int idx = blockIdx.x * 256 + threadIdx.x;   // 4096
    float s = 0.0f;
    #pragma unroll 2
    for (int b = 0; b < NKB; ++b) s += g_Spart[(size_t)b * 4096 + idx];
    g_S[idx] = s;
}

// ------------------------------------------------------------- final scalar
__global__ void k_final(float* __restrict__ out) {
    const int tid = threadIdx.x;
    float tot = 0.0f, diag = 0.0f;
    for (int idx = tid; idx < 4096; idx += 256) {
        int i = idx >> 6, j = idx & 63;
        float ce = (g_L[i] - g_S[idx]) * (1.0f / 196.0f);
        tot += ce;
        if (i == j) diag += ce;
    }
    #pragma unroll
    for (int o = 16; o; o >>= 1) {
        tot  += __shfl_xor_sync(0xffffffffu, tot,  o);
        diag += __shfl_xor_sync(0xffffffffu, diag, o);
    }
    __shared__ float rt[8], rd[8];
    if ((tid & 31) == 0) { rt[tid >> 5] = tot; rd[tid >> 5] = diag; }
    __syncthreads();
    if (tid == 0) {
        float T = 0.0f, D = 0.0f;
        #pragma unroll
        for (int w = 0; w < 8; ++w) { T += rt[w]; D += rd[w]; }
        out[0] = (D / 64.0f) / ((T - D) / 4032.0f);
    }
}

// ---------------------------------------------------------------------------
extern "C" void kernel_launch(void* const* d_in, const int* in_sizes, int n_in,
                              void* d_out, int out_size) {
    const float* x  = (const float*)d_in[0];
    const float* y  = (const float*)d_in[1];
    const float* Wc = (const float*)d_in[2];
    const float* b  = (const float*)d_in[3];
    float* out = (float*)d_out;

    const int SM_S = 2 * 64 * SPAD * 2;   // 67584 B

    cudaFuncSetAttribute(k_gemm, cudaFuncAttributeMaxDynamicSharedMemorySize, SM_GEMM);
    cudaFuncSetAttribute(k_sgemm, cudaFuncAttributeMaxDynamicSharedMemorySize, SM_S);

    k_prep_w<<<(KDIM * HID + 255) / 256, 256>>>(Wc);
    k_gemm<<<dim3(196, 2), 256, SM_GEMM>>>(x, y, b);
    k_reduceL<<<BSZ, 256>>>();
    k_sgemm<<<NKB, 256, SM_S>>>();
    k_sreduce<<<16, 256>>>();
    k_final<<<1, 256>>>(out);
}

// round 12
// speedup vs baseline: 1.6604x; 1.1807x over previous
#include <cuda_runtime.h>
#include <cuda_bf16.h>
#include <math.h>
#include <stdint.h>

// ---------------------------------------------------------------------------
// PairContrastiveLoss via mma.sync (HMMA bf16), fused softmax/lse epilogue.
//   emb = im2col(x|y) @ W^T + b   (A: fp32 cp.async + in-reg bf16 cvt)
//   CE[i,j] = (L[i] - S[i,j]) / 196,  S = Xp_raw @ q^T, L[i] = sum_p lse
//   out = (trace/B) / ((sum-trace)/(B^2-B))
// R12: APITCH=44 (conflict-free A STS), double-buffered k_sgemm,
//      2-stage deterministic k_sreduce.
// ---------------------------------------------------------------------------

#define BSZ   64
#define NP    196
#define HID   384
#define KDIM  768
#define MROWS 12544
#define KTOT  75264
#define SK    256          // k-chunk for S gemm
#define NKB   294          // KTOT / SK
#define NS    7            // sreduce stage-1 chunks (42 blocks each)

__device__ __nv_bfloat16 g_Wt[KDIM * HID];                  // [k][n] bf16
__device__ __nv_bfloat16 g_Xb[(size_t)MROWS * HID];         // raw x logits bf16
__device__ __nv_bfloat16 g_Qb[(size_t)MROWS * HID];         // q = softmax(y) bf16
__device__ float g_lse[MROWS];
__device__ float g_L[BSZ];
__device__ float g_Spart[NKB * 4096];
__device__ float g_S2[NS * 4096];

// ------------------------------------------------------------- PTX helpers
__device__ __forceinline__ uint32_t smem_u32(const void* p) {
    uint32_t a;
    asm("{ .reg .u64 t; cvta.to.shared.u64 t, %1; cvt.u32.u64 %0, t; }"
        : "=r"(a) : "l"(p));
    return a;
}
__device__ __forceinline__ void cp_async16(uint32_t dst, const void* src) {
    asm volatile("cp.async.cg.shared.global [%0], [%1], 16;" :: "r"(dst), "l"(src));
}
#define CP_COMMIT() asm volatile("cp.async.commit_group;" ::: "memory")
#define CP_WAIT(n)  asm volatile("cp.async.wait_group %0;" :: "n"(n) : "memory")

__device__ __forceinline__ void ldm_x4(uint32_t* r, uint32_t addr) {
    asm volatile("ldmatrix.sync.aligned.m8n8.x4.shared.b16 {%0,%1,%2,%3}, [%4];"
        : "=r"(r[0]), "=r"(r[1]), "=r"(r[2]), "=r"(r[3]) : "r"(addr));
}
__device__ __forceinline__ void ldm_x4t(uint32_t* r, uint32_t addr) {
    asm volatile("ldmatrix.sync.aligned.m8n8.x4.trans.shared.b16 {%0,%1,%2,%3}, [%4];"
        : "=r"(r[0]), "=r"(r[1]), "=r"(r[2]), "=r"(r[3]) : "r"(addr));
}
__device__ __forceinline__ void mma16816(float* d, const uint32_t* a,
                                         uint32_t b0, uint32_t b1) {
    asm volatile(
        "mma.sync.aligned.m16n8k16.row.col.f32.bf16.bf16.f32 "
        "{%0,%1,%2,%3}, {%4,%5,%6,%7}, {%8,%9}, {%0,%1,%2,%3};"
        : "+f"(d[0]), "+f"(d[1]), "+f"(d[2]), "+f"(d[3])
        : "r"(a[0]), "r"(a[1]), "r"(a[2]), "r"(a[3]), "r"(b0), "r"(b1));
}
__device__ __forceinline__ uint32_t packbf(float2 v) {
    __nv_bfloat162 p = __floats2bfloat162_rn(v.x, v.y);
    return *(uint32_t*)&p;
}

// ------------------------------------------------------------------ prep W
__global__ void k_prep_w(const float* __restrict__ Wc) {
    int idx = blockIdx.x * 256 + threadIdx.x;
    if (idx < KDIM * HID) {
        int k = idx / HID, n = idx - k * HID;
        g_Wt[idx] = __float2bfloat16_rn(Wc[n * KDIM + k]);
    }
}

// ------------------------------------------------ HMMA patch-embed GEMM
// CTA: BM=64 x BN=384 (full N), BK=32, 24 k-iters, 8 warps (2m x 4n).
// 3-stage cp.async (A fp32 + B bf16), single barrier per iter, 2 CTAs/SM.
#define APITCH 44                        // fp32 pitch: conflict-free STS + LDS
#define BPAD   392
#define A_ST   (64 * APITCH * 4)         // 11264 B per stage (fp32)
#define B_ST   (32 * BPAD * 2)           // 25088 B per stage
#define NSTG   3
#define SM_B0  (NSTG * A_ST)             // 33792
#define SM_GEMM (NSTG * (A_ST + B_ST))   // 109056 B

__global__ void __launch_bounds__(256, 2) k_gemm(
        const float* __restrict__ x, const float* __restrict__ y,
        const float* __restrict__ bias) {
    extern __shared__ char smem[];
    const uint32_t sb = smem_u32(smem);
    const int tid = threadIdx.x;
    const int lane = tid & 31;
    const int wid = tid >> 5;
    const int wm = wid >> 2;            // 0..1
    const int wn = wid & 3;             // 0..3
    const int m0 = blockIdx.x * 64;
    const int img = blockIdx.y;
    const float* im = img ? y : x;

    // ---- A cp.async geometry
    const int r_a = tid >> 3;           // 0..31 (it adds +32)
    const int rr  = (tid >> 2) & 1;
    const int seg = tid & 3;
    int baseA[2];
    uint32_t dstA[2];
    #pragma unroll
    for (int it = 0; it < 2; ++it) {
        int row = r_a + it * 32;
        int m = m0 + row;
        int b = m / NP, p = m - b * NP;
        int ph = p / 14, pw = p - ph * 14;
        baseA[it] = (b * 3 * 224 + ph * 16) * 224 + pw * 16 + rr * 224 + seg * 4;
        dstA[it]  = (row * APITCH + rr * 16 + seg * 4) * 4;
    }

    float acc[2][12][4] = {};

    auto issueStage = [&](int j, int buf) {
        const uint32_t aB = sb + buf * A_ST;
        const uint32_t bB = sb + SM_B0 + buf * B_ST;
        const int c = j >> 3, r2 = (j & 7) * 2;
        const int srcOff = c * 50176 + r2 * 224;
        #pragma unroll
        for (int it = 0; it < 2; ++it)
            cp_async16(aB + dstA[it], im + baseA[it] + srcOff);
        #pragma unroll
        for (int it = 0; it < 6; ++it) {
            int idx = tid + it * 256;
            int row = idx / 48, sg = idx - row * 48;
            cp_async16(bB + row * (BPAD * 2) + sg * 16,
                       g_Wt + (size_t)(j * 32 + row) * HID + sg * 8);
        }
        CP_COMMIT();
    };

    issueStage(0, 0);
    issueStage(1, 1);

    const int gr = lane >> 2;           // A frag row-in-8
    const int tg = (lane & 3) * 2;      // A frag col pair

    for (int j = 0; j < 24; ++j) {
        const int buf = j % NSTG;
        if (j < 23) { CP_WAIT(1); } else { CP_WAIT(0); }
        __syncthreads();
        if (j < 22) issueStage(j + 2, (j + 2) % NSTG);

        const float* Af = (const float*)(smem + buf * A_ST);
        const uint32_t bBase = sb + SM_B0 + buf * B_ST;
        #pragma unroll
        for (int kf2 = 0; kf2 < 2; ++kf2) {
            const int kf = kf2 * 16;
            uint32_t a[2][4];
            #pragma unroll
            for (int mf = 0; mf < 2; ++mf) {
                const float* base = Af + (wm * 32 + mf * 16) * APITCH + kf + tg;
                a[mf][0] = packbf(*(const float2*)(base + gr * APITCH));
                a[mf][1] = packbf(*(const float2*)(base + (gr + 8) * APITCH));
                a[mf][2] = packbf(*(const float2*)(base + gr * APITCH + 8));
                a[mf][3] = packbf(*(const float2*)(base + (gr + 8) * APITCH + 8));
            }
            #pragma unroll
            for (int nf2 = 0; nf2 < 6; ++nf2) {
                uint32_t bb[4];
                uint32_t bd = bBase +
                    ((kf + (lane & 15)) * BPAD + wn * 96 + nf2 * 16 + ((lane >> 4) << 3)) * 2;
                ldm_x4t(bb, bd);
                mma16816(acc[0][nf2 * 2 + 0], a[0], bb[0], bb[1]);
                mma16816(acc[0][nf2 * 2 + 1], a[0], bb[2], bb[3]);
                mma16816(acc[1][nf2 * 2 + 0], a[1], bb[0], bb[1]);
                mma16816(acc[1][nf2 * 2 + 1], a[1], bb[2], bb[3]);
            }
        }
    }
    __syncthreads();

    // ================= fused epilogue: bias + softmax/lse =================
    const int qid = lane >> 2, tc = lane & 3;

    #pragma unroll
    for (int nf = 0; nf < 12; ++nf) {
        float2 bv = *(const float2*)(bias + wn * 96 + nf * 8 + tc * 2);
        #pragma unroll
        for (int mf = 0; mf < 2; ++mf) {
            acc[mf][nf][0] += bv.x; acc[mf][nf][1] += bv.y;
            acc[mf][nf][2] += bv.x; acc[mf][nf][3] += bv.y;
        }
    }

    float* sMax = (float*)smem;              // [64][4]
    float* sSum = (float*)(smem + 1024);     // [64][4]

    float mx[2][2];
    #pragma unroll
    for (int mf = 0; mf < 2; ++mf)
        #pragma unroll
        for (int h = 0; h < 2; ++h) {
            float m = -1e30f;
            #pragma unroll
            for (int nf = 0; nf < 12; ++nf)
                m = fmaxf(m, fmaxf(acc[mf][nf][h * 2], acc[mf][nf][h * 2 + 1]));
            m = fmaxf(m, __shfl_xor_sync(0xffffffffu, m, 1));
            m = fmaxf(m, __shfl_xor_sync(0xffffffffu, m, 2));
            mx[mf][h] = m;
        }
    if (tc == 0) {
        #pragma unroll
        for (int mf = 0; mf < 2; ++mf)
            #pragma unroll
            for (int h = 0; h < 2; ++h)
                sMax[(wm * 32 + mf * 16 + h * 8 + qid) * 4 + wn] = mx[mf][h];
    }
    __syncthreads();
    float gmx[2][2];
    #pragma unroll
    for (int mf = 0; mf < 2; ++mf)
        #pragma unroll
        for (int h = 0; h < 2; ++h) {
            const float* r = &sMax[(wm * 32 + mf * 16 + h * 8 + qid) * 4];
            gmx[mf][h] = fmaxf(fmaxf(r[0], r[1]), fmaxf(r[2], r[3]));
        }
    float sm[2][2];
    #pragma unroll
    for (int mf = 0; mf < 2; ++mf)
        #pragma unroll
        for (int h = 0; h < 2; ++h) {
            float s = 0.0f;
            #pragma unroll
            for (int nf = 0; nf < 12; ++nf)
                s += __expf(acc[mf][nf][h * 2] - gmx[mf][h])
                   + __expf(acc[mf][nf][h * 2 + 1] - gmx[mf][h]);
            s += __shfl_xor_sync(0xffffffffu, s, 1);
            s += __shfl_xor_sync(0xffffffffu, s, 2);
            sm[mf][h] = s;
        }
    __syncthreads();
    if (tc == 0) {
        #pragma unroll
        for (int mf = 0; mf < 2; ++mf)
            #pragma unroll
            for (int h = 0; h < 2; ++h)
                sSum[(wm * 32 + mf * 16 + h * 8 + qid) * 4 + wn] = sm[mf][h];
    }
    __syncthreads();

    __nv_bfloat16* dst = img ? g_Qb : g_Xb;
    #pragma unroll
    for (int mf = 0; mf < 2; ++mf) {
        #pragma unroll
        for (int h = 0; h < 2; ++h) {
            const int mloc = wm * 32 + mf * 16 + h * 8 + qid;
            const int row = m0 + mloc;
            const float* r = &sSum[mloc * 4];
            const float den = r[0] + r[1] + r[2] + r[3];
            if (img == 0) {
                if (wn == 0 && tc == 0) g_lse[row] = gmx[mf][h] + __logf(den);
                #pragma unroll
                for (int nf = 0; nf < 12; ++nf) {
                    __nv_bfloat162 p = __floats2bfloat162_rn(
                        acc[mf][nf][h * 2], acc[mf][nf][h * 2 + 1]);
                    *(uint32_t*)(dst + (size_t)row * HID + wn * 96 + nf * 8 + tc * 2)
                        = *(uint32_t*)&p;
                }
            } else {
                const float inv = 1.0f / den;
                const float g = gmx[mf][h];
                #pragma unroll
                for (int nf = 0; nf < 12; ++nf) {
                    __nv_bfloat162 p = __floats2bfloat162_rn(
                        __expf(acc[mf][nf][h * 2] - g) * inv,
                        __expf(acc[mf][nf][h * 2 + 1] - g) * inv);
                    *(uint32_t*)(dst + (size_t)row * HID + wn * 96 + nf * 8 + tc * 2)
                        = *(uint32_t*)&p;
                }
            }
        }
    }
}

// ----------------------------------------------------- L[b] = sum_p lse[b,p]
__global__ void k_reduceL() {
    const int b = blockIdx.x;
    const int tid = threadIdx.x;
    float v = (tid < NP) ? g_lse[b * NP + tid] : 0.0f;
    #pragma unroll
    for (int o = 16; o; o >>= 1) v += __shfl_xor_sync(0xffffffffu, v, o);
    __shared__ float red[8];
    if ((tid & 31) == 0) red[tid >> 5] = v;
    __syncthreads();
    if (tid == 0) {
        float s = 0.0f;
        #pragma unroll
        for (int w = 0; w < 8; ++w) s += red[w];
        g_L[b] = s;
    }
}

// ---------------- S partials via HMMA: block = 256-wide k slice, 2x128 dbuf
#define HPAD 136                        // 128 + 8 elems per half
#define H_SZ (64 * HPAD * 2)            // 17408 B per array per half
__global__ void __launch_bounds__(256) k_sgemm() {
    extern __shared__ char sh[];
    // layout: X0 | Q0 | X1 | Q1
    const uint32_t sbase = smem_u32(sh);
    const int tid = threadIdx.x;
    const int lane = tid & 31;
    const int wid = tid >> 5;
    const int wm2 = wid >> 1;           // 0..3
    const int wn2 = wid & 1;            // 0..1

    const int kb16 = blockIdx.x * 32;   // uint4 offset of this block's k-slice

    auto issueHalf = [&](int half) {
        const uint32_t xB = sbase + half * 2 * H_SZ;
        const uint32_t qB = xB + H_SZ;
        const __nv_bfloat16* Xg = g_Xb;
        const __nv_bfloat16* Qg = g_Qb;
        #pragma unroll
        for (int it = 0; it < 4; ++it) {
            int u = tid + it * 256;
            int row = u >> 4, un = u & 15;
            size_t src = (size_t)row * 9408 + kb16 + half * 16 + un;
            cp_async16(xB + (row * HPAD + un * 8) * 2, (const uint4*)Xg + src);
            cp_async16(qB + (row * HPAD + un * 8) * 2, (const uint4*)Qg + src);
        }
        CP_COMMIT();
    };

    issueHalf(0);
    issueHalf(1);

    float acc[4][4] = {};
    #pragma unroll
    for (int half = 0; half < 2; ++half) {
        if (half == 0) { CP_WAIT(1); } else { CP_WAIT(0); }
        __syncthreads();
        const uint32_t xb = sbase + half * 2 * H_SZ;
        const uint32_t qb = xb + H_SZ;
        #pragma unroll 4
        for (int ks = 0; ks < 8; ++ks) {
            const uint32_t koff = (ks * 16 + ((lane >> 4) << 3)) * 2;
            uint32_t a[4], b0[4], b1[4];
            ldm_x4(a,  xb + (wm2 * 16 + (lane & 15)) * (HPAD * 2) + koff);
            ldm_x4(b0, qb + (wn2 * 32 + (lane & 15)) * (HPAD * 2) + koff);
            ldm_x4(b1, qb + (wn2 * 32 + 16 + (lane & 15)) * (HPAD * 2) + koff);
            mma16816(acc[0], a, b0[0], b0[1]);
            mma16816(acc[1], a, b0[2], b0[3]);
            mma16816(acc[2], a, b1[0], b1[1]);
            mma16816(acc[3], a, b1[2], b1[3]);
        }
        if (half == 0) __syncthreads();
    }

    float* dst = g_Spart + (size_t)blockIdx.x * 4096;
    const int qid = lane >> 2, tc = lane & 3;
    #pragma unroll
    for (int t = 0; t < 4; ++t) {
        int i0 = wm2 * 16 + qid;
        int j  = wn2 * 32 + t * 8 + tc * 2;
        *(float2*)(dst + i0 * 64 + j)       = make_float2(acc[t][0], acc[t][1]);
        *(float2*)(dst + (i0 + 8) * 64 + j) = make_float2(acc[t][2], acc[t][3]);
    }
}

// ------------------- 2-stage deterministic partial reduction
__global__ void k_sreduce() {
    int idx = blockIdx.x * 256 + threadIdx.x;   // 4096 per chunk
    int c = blockIdx.y;                         // 0..NS-1
    float s = 0.0f;
    #pragma unroll 2
    for (int b = c * 42; b < (c + 1) * 42; ++b)
        s += g_Spart[(size_t)b * 4096 + idx];
    g_S2[c * 4096 + idx] = s;
}

// ------------------------------------------------------------- final scalar
__global__ void k_final(float* __restrict__ out) {
    const int tid = threadIdx.x;
    float tot = 0.0f, diag = 0.0f;
    for (int idx = tid; idx < 4096; idx += 256) {
        float S = 0.0f;
        #pragma unroll
        for (int c = 0; c < NS; ++c) S += g_S2[c * 4096 + idx];
        int i = idx >> 6, j = idx & 63;
        float ce = (g_L[i] - S) * (1.0f / 196.0f);
        tot += ce;
        if (i == j) diag += ce;
    }
    #pragma unroll
    for (int o = 16; o; o >>= 1) {
        tot  += __shfl_xor_sync(0xffffffffu, tot,  o);
        diag += __shfl_xor_sync(0xffffffffu, diag, o);
    }
    __shared__ float rt[8], rd[8];
    if ((tid & 31) == 0) { rt[tid >> 5] = tot; rd[tid >> 5] = diag; }
    __syncthreads();
    if (tid == 0) {
        float T = 0.0f, D = 0.0f;
        #pragma unroll
        for (int w = 0; w < 8; ++w) { T += rt[w]; D += rd[w]; }
        out[0] = (D / 64.0f) / ((T - D) / 4032.0f);
    }
}

// ---------------------------------------------------------------------------
extern "C" void kernel_launch(void* const* d_in, const int* in_sizes, int n_in,
                              void* d_out, int out_size) {
    const float* x  = (const float*)d_in[0];
    const float* y  = (const float*)d_in[1];
    const float* Wc = (const float*)d_in[2];
    const float* b  = (const float*)d_in[3];
    float* out = (float*)d_out;

    const int SM_S = 4 * H_SZ;            // 69632 B

    cudaFuncSetAttribute(k_gemm, cudaFuncAttributeMaxDynamicSharedMemorySize, SM_GEMM);
    cudaFuncSetAttribute(k_sgemm, cudaFuncAttributeMaxDynamicSharedMemorySize, SM_S);

    k_prep_w<<<(KDIM * HID + 255) / 256, 256>>>(Wc);
    k_gemm<<<dim3(196, 2), 256, SM_GEMM>>>(x, y, b);
    k_reduceL<<<BSZ, 256>>>();
    k_sgemm<<<NKB, 256, SM_S>>>();
    k_sreduce<<<dim3(16, NS), 256>>>();
    k_final<<<1, 256>>>(out);
}